// round 1
// baseline (speedup 1.0000x reference)
#include <cuda_runtime.h>

#define Bb 512
#define Nn 10020
#define Ll 20
#define Ss 10
#define Hh 1001
#define HL 20020            // Hh * Ll
#define INV_SQRT6 0.40824829046386296f

// Output partition offsets (floats) in d_out, concat order:
// reconstructed, P, p1, p2, st, rot_axes, nw, contribution
#define O_REC 0
#define O_P   15390720
#define O_P1  16928256
#define O_P2  18465792
#define O_ST  20003328
#define O_ROT 50754048
#define O_NW  81504768
#define O_CB  91534788

// small precompute tables
__device__ float g_cos[HL];
__device__ float g_sin[HL];
__device__ float g_rowsum[Nn];

// ---------------------------------------------------------------------------
// Kernel 0: trig tables + rowsum table
// ---------------------------------------------------------------------------
__global__ void k_tables(const float* __restrict__ angles,
                         const float* __restrict__ W_enc)
{
    int idx = blockIdx.x * blockDim.x + threadIdx.x;
    if (idx < HL) {
        float a = angles[idx];
        g_cos[idx] = cosf(a);
        g_sin[idx] = sinf(a);
    }
    if (idx < Nn) {
        int n = idx;
        int ha = n / Ss;          // l = n%10
        int hb = ha - 1;          // l = n%10 + 10
        float rs = 0.f;
        if (ha < Hh) rs += W_enc[((n % Ss) * Hh + ha) * 3 + 0];
        if (hb >= 0) rs += W_enc[((n % Ss + Ss) * Hh + hb) * 3 + 0];
        g_rowsum[n] = rs;
    }
}

// ---------------------------------------------------------------------------
// Kernel A: per (b, h): emb -> P, p1, p2, p12; writes P, p1, p2, st, rot_axes
// block = 128 threads (128 consecutive h), grid = (ceil(H/128), B)
// ---------------------------------------------------------------------------
#define HBLK 128
__global__ void k_encode(const float* __restrict__ x,
                         const float* __restrict__ W_enc,
                         const float* __restrict__ W_dec,
                         float* __restrict__ out)
{
    __shared__ float sx[(Ss * HBLK + Ll - Ss) * 3];   // 1290*3 floats
    const int b   = blockIdx.y;
    const int h0  = blockIdx.x * HBLK;
    const int tid = threadIdx.x;

    const int base = Ss * h0;
    const int span = Ss * HBLK + Ll - Ss;             // 1290 positions
    for (int i = tid; i < span * 3; i += HBLK) {
        int pos = base + i / 3;
        sx[i] = (pos < Nn) ? x[(b * Nn + pos) * 3 + (i % 3)] : 0.f;
    }
    __syncthreads();

    const int h = h0 + tid;
    if (h >= Hh) return;

    // emb[l][k] = sum_i x[b, 10h+i, k] * W_enc[i, h, l]
    float e00=0,e01=0,e02=0, e10=0,e11=0,e12=0, e20=0,e21=0,e22=0;
    const int lo = Ss * tid;
#pragma unroll
    for (int i = 0; i < Ll; i++) {
        const float* w = &W_enc[(i * Hh + h) * 3];
        float w0 = w[0], w1 = w[1], w2 = w[2];
        float x0 = sx[(lo + i) * 3 + 0];
        float x1 = sx[(lo + i) * 3 + 1];
        float x2 = sx[(lo + i) * 3 + 2];
        e00 += x0 * w0; e01 += x1 * w0; e02 += x2 * w0;
        e10 += x0 * w1; e11 += x1 * w1; e12 += x2 * w1;
        e20 += x0 * w2; e21 += x1 * w2; e22 += x2 * w2;
        // st[b, i, h, k]
        int sti = ((b * Ll + i) * Hh + h) * 3;
        out[O_ST + sti + 0] = x0;
        out[O_ST + sti + 1] = x1;
        out[O_ST + sti + 2] = x2;
    }

    // P, I1, I2
    float Px = e00, Py = e01, Pz = e02;
    float d1x = e10 - Px, d1y = e11 - Py, d1z = e12 - Pz;
    float d2x = e20 - Px, d2y = e21 - Py, d2z = e22 - Pz;
    float n1 = sqrtf(d1x*d1x + d1y*d1y + d1z*d1z); if (n1 == 0.f) n1 = 1.f;
    float n2 = sqrtf(d2x*d2x + d2y*d2y + d2z*d2z); if (n2 == 0.f) n2 = 1.f;
    float i1 = 1.f / n1, i2 = 1.f / n2;
    float p1x = d1x*i1, p1y = d1y*i1, p1z = d1z*i1;
    float p2x = d2x*i2, p2y = d2y*i2, p2z = d2z*i2;
    float cx = (p1y*p2z - p1z*p2y) * INV_SQRT6;
    float cy = (p1z*p2x - p1x*p2z) * INV_SQRT6;
    float cz = (p1x*p2y - p1y*p2x) * INV_SQRT6;

    int pb = (b * Hh + h) * 3;
    out[O_P  + pb + 0] = Px;  out[O_P  + pb + 1] = Py;  out[O_P  + pb + 2] = Pz;
    out[O_P1 + pb + 0] = p1x; out[O_P1 + pb + 1] = p1y; out[O_P1 + pb + 2] = p1z;
    out[O_P2 + pb + 0] = p2x; out[O_P2 + pb + 1] = p2y; out[O_P2 + pb + 2] = p2z;

    // rot_axes[b, h, l, k] = p1*Wd[0,h,l] + p2*Wd[1,h,l] + p12*Wd[2,h,l]
#pragma unroll
    for (int l = 0; l < Ll; l++) {
        float w0 = W_dec[(0 * Hh + h) * Ll + l];
        float w1 = W_dec[(1 * Hh + h) * Ll + l];
        float w2 = W_dec[(2 * Hh + h) * Ll + l];
        int rb = ((b * Hh + h) * Ll + l) * 3;
        out[O_ROT + rb + 0] = p1x * w0 + p2x * w1 + cx * w2;
        out[O_ROT + rb + 1] = p1y * w0 + p2y * w1 + cy * w2;
        out[O_ROT + rb + 2] = p1z * w0 + p2z * w1 + cz * w2;
    }
}

// ---------------------------------------------------------------------------
// Kernel C: per (b, n): gather <=2 (h,l) contributions -> reconstructed
// grid = (ceil(N/256), B)
// ---------------------------------------------------------------------------
__global__ void k_recon(const float* __restrict__ W_enc,
                        const float* __restrict__ scaling,
                        float* __restrict__ out)
{
    const int n = blockIdx.x * blockDim.x + threadIdx.x;
    if (n >= Nn) return;
    const int b = blockIdx.y;

    const float inv_rs = 1.f / g_rowsum[n];
    const float sc = scaling[n];          // scaling[10h+l] == scaling[n]
    const int h0 = n / Ss, l0 = n % Ss;

    float a0 = 0.f, a1 = 0.f, a2 = 0.f;
#pragma unroll
    for (int c = 0; c < 2; c++) {
        int h = h0 - c;
        int l = l0 + Ss * c;
        if (h < 0 || h >= Hh) continue;

        float nwg = W_enc[(l * Hh + h) * 3 + 0] * inv_rs;
        int ai = h * Ll + l;
        float qw = g_cos[ai];
        float s  = g_sin[ai];

        int rb = ((b * Hh + h) * Ll + l) * 3;
        float qx = s * out[O_ROT + rb + 0];
        float qy = s * out[O_ROT + rb + 1];
        float qz = s * out[O_ROT + rb + 2];

        int pb = (b * Hh + h) * 3;
        float vx = out[O_P1 + pb + 0];
        float vy = out[O_P1 + pb + 1];
        float vz = out[O_P1 + pb + 2];

        // t = q * (0, v)
        float tw = -qx*vx - qy*vy - qz*vz;
        float tx =  qw*vx + qy*vz - qz*vy;
        float ty =  qw*vy + qz*vx - qx*vz;
        float tz =  qw*vz + qx*vy - qy*vx;
        // r = t * conj(q), vector part
        float rx = -tw*qx + tx*qw - ty*qz + tz*qy;
        float ry = -tw*qy + ty*qw - tz*qx + tx*qz;
        float rz = -tw*qz + tz*qw - tx*qy + ty*qx;

        float Px = out[O_P + pb + 0];
        float Py = out[O_P + pb + 1];
        float Pz = out[O_P + pb + 2];
        a0 += (sc * rx + Px) * nwg;
        a1 += (sc * ry + Py) * nwg;
        a2 += (sc * rz + Pz) * nwg;
    }
    int ob = (b * Nn + n) * 3;
    out[O_REC + ob + 0] = a0;
    out[O_REC + ob + 1] = a1;
    out[O_REC + ob + 2] = a2;
}

// ---------------------------------------------------------------------------
// Kernel D: per (n, h): nw + contribution
// grid = (ceil(H/256), N)
// ---------------------------------------------------------------------------
__global__ void k_nw(const float* __restrict__ W_enc,
                     float* __restrict__ out)
{
    const int h = blockIdx.x * blockDim.x + threadIdx.x;
    if (h >= Hh) return;
    const int n = blockIdx.y;

    const int started = (n < Nn - Ll) ? (n / Ss + 1) : (Hh);     // started[10000]=1001
    const int ended   = (n >= Ll) ? ((n - Ss) / Ss) : 0;
    const float contrib = (h >= ended && h < started) ? 1.f : 0.f;

    const int shift = n - Ss * h;
    const bool valid = (shift >= 0) && (shift < Ll);
    int cs = shift < 0 ? 0 : (shift > Ll - 1 ? Ll - 1 : shift);
    float gathered = W_enc[(cs * Hh + h) * 3 + 0];
    float nwv = valid ? (contrib * gathered) / g_rowsum[n] : 0.f;

    size_t o = (size_t)n * Hh + h;
    out[O_NW + o] = nwv;
    out[O_CB + o] = contrib;
}

// ---------------------------------------------------------------------------
extern "C" void kernel_launch(void* const* d_in, const int* in_sizes, int n_in,
                              void* d_out, int out_size)
{
    const float* x       = (const float*)d_in[0];
    const float* W_enc   = (const float*)d_in[1];
    const float* W_dec   = (const float*)d_in[2];
    const float* angles  = (const float*)d_in[3];
    const float* scaling = (const float*)d_in[4];
    float* out = (float*)d_out;

    k_tables<<<(HL + 255) / 256, 256>>>(angles, W_enc);

    dim3 gA((Hh + HBLK - 1) / HBLK, Bb);
    k_encode<<<gA, HBLK>>>(x, W_enc, W_dec, out);

    dim3 gC((Nn + 255) / 256, Bb);
    k_recon<<<gC, 256>>>(W_enc, scaling, out);

    dim3 gD((Hh + 255) / 256, Nn);
    k_nw<<<gD, 256>>>(W_enc, out);
}

// round 2
// speedup vs baseline: 1.1428x; 1.1428x over previous
#include <cuda_runtime.h>

#define Bb 512
#define Nn 10020
#define Ll 20
#define Ss 10
#define Hh 1001
#define HL 20020            // Hh * Ll
#define INV_SQRT6 0.40824829046386296f

// Output partition offsets (floats) in d_out, concat order:
// reconstructed, P, p1, p2, st, rot_axes, nw, contribution
#define O_REC 0
#define O_P   15390720
#define O_P1  16928256
#define O_P2  18465792
#define O_ST  20003328
#define O_ROT 50754048
#define O_NW  81504768
#define O_CB  91534788

// precompute tables
__device__ float4 g_t0[HL];   // (cos, sin, nw_g, scaling)
__device__ float4 g_t1[HL];   // (Wd0, Wd1, Wd2, 0)
__device__ float  g_rowsum[Nn];

// ---------------------------------------------------------------------------
// Kernel 0: per-(h,l) constant tables + rowsum table
// ---------------------------------------------------------------------------
__global__ void k_tables(const float* __restrict__ angles,
                         const float* __restrict__ W_enc,
                         const float* __restrict__ W_dec,
                         const float* __restrict__ scaling)
{
    int idx = blockIdx.x * blockDim.x + threadIdx.x;
    if (idx < HL) {
        int h = idx / Ll, l = idx % Ll;
        int n = Ss * h + l;                 // atom index
        int ha = n / Ss, l0 = n % Ss;
        float rs = 0.f;
        if (ha < Hh) rs += W_enc[(l0 * Hh + ha) * 3];
        if (ha >= 1) rs += W_enc[((l0 + Ss) * Hh + (ha - 1)) * 3];
        float a = angles[idx];
        float4 t0;
        t0.x = cosf(a);
        t0.y = sinf(a);
        t0.z = W_enc[(l * Hh + h) * 3] / rs;
        t0.w = scaling[n];
        g_t0[idx] = t0;
        float4 t1;
        t1.x = W_dec[(0 * Hh + h) * Ll + l];
        t1.y = W_dec[(1 * Hh + h) * Ll + l];
        t1.z = W_dec[(2 * Hh + h) * Ll + l];
        t1.w = 0.f;
        g_t1[idx] = t1;
    }
    if (idx < Nn) {
        int n = idx;
        int ha = n / Ss;
        float rs = 0.f;
        if (ha < Hh) rs += W_enc[((n % Ss) * Hh + ha) * 3];
        if (ha >= 1) rs += W_enc[((n % Ss + Ss) * Hh + ha - 1) * 3];
        g_rowsum[n] = rs;
    }
}

// ---------------------------------------------------------------------------
// Fused kernel: emb -> P/p1/p2/st/rot_axes AND reconstructed (scatter via SMEM)
// block = 128 threads (consecutive h), grid = (ceil(H/128), B)
// ---------------------------------------------------------------------------
#define HBLK 128
#define SPANF ((Ss * HBLK + Ll - Ss) * 3)   // 1290 positions * 3 = 3870 floats

__global__ void k_encode(const float* __restrict__ x,
                         const float* __restrict__ W_enc,
                         float* __restrict__ out)
{
    __shared__ float sx [SPANF];
    __shared__ float acc[SPANF];

    const int b   = blockIdx.y;
    const int h0  = blockIdx.x * HBLK;
    const int tid = threadIdx.x;
    const int base = Ss * h0;

    // stage x window + zero accumulator
    const int xb = b * Nn * 3 + base * 3;
    for (int i = tid; i < SPANF; i += HBLK) {
        int pos = base + i / 3;
        sx[i]  = (pos < Nn) ? x[xb + i] : 0.f;
        acc[i] = 0.f;
    }
    __syncthreads();

    const int h = h0 + tid;
    const bool active = (h < Hh);
    float r[60];

    if (active) {
        // emb[l][k] = sum_i x[b, 10h+i, k] * W_enc[i, h, l]  + st writes
        float e00=0,e01=0,e02=0, e10=0,e11=0,e12=0, e20=0,e21=0,e22=0;
        const int lo = 30 * tid;
#pragma unroll
        for (int i = 0; i < Ll; i++) {
            const float* w = &W_enc[(i * Hh + h) * 3];
            float w0 = w[0], w1 = w[1], w2 = w[2];
            float x0 = sx[lo + 3*i + 0];
            float x1 = sx[lo + 3*i + 1];
            float x2 = sx[lo + 3*i + 2];
            e00 += x0 * w0; e01 += x1 * w0; e02 += x2 * w0;
            e10 += x0 * w1; e11 += x1 * w1; e12 += x2 * w1;
            e20 += x0 * w2; e21 += x1 * w2; e22 += x2 * w2;
            int sti = O_ST + ((b * Ll + i) * Hh + h) * 3;
            out[sti + 0] = x0;
            out[sti + 1] = x1;
            out[sti + 2] = x2;
        }

        float Px = e00, Py = e01, Pz = e02;
        float d1x = e10 - Px, d1y = e11 - Py, d1z = e12 - Pz;
        float d2x = e20 - Px, d2y = e21 - Py, d2z = e22 - Pz;
        float n1 = sqrtf(d1x*d1x + d1y*d1y + d1z*d1z); if (n1 == 0.f) n1 = 1.f;
        float n2 = sqrtf(d2x*d2x + d2y*d2y + d2z*d2z); if (n2 == 0.f) n2 = 1.f;
        float i1 = 1.f / n1, i2 = 1.f / n2;
        float p1x = d1x*i1, p1y = d1y*i1, p1z = d1z*i1;
        float p2x = d2x*i2, p2y = d2y*i2, p2z = d2z*i2;
        float cx = (p1y*p2z - p1z*p2y) * INV_SQRT6;
        float cy = (p1z*p2x - p1x*p2z) * INV_SQRT6;
        float cz = (p1x*p2y - p1y*p2x) * INV_SQRT6;

        int pb = (b * Hh + h) * 3;
        out[O_P  + pb + 0] = Px;  out[O_P  + pb + 1] = Py;  out[O_P  + pb + 2] = Pz;
        out[O_P1 + pb + 0] = p1x; out[O_P1 + pb + 1] = p1y; out[O_P1 + pb + 2] = p1z;
        out[O_P2 + pb + 0] = p2x; out[O_P2 + pb + 1] = p2y; out[O_P2 + pb + 2] = p2z;

        // rot_axes + reconstruction contributions (kept in registers)
#pragma unroll
        for (int l = 0; l < Ll; l++) {
            float4 t1 = g_t1[h * Ll + l];
            float rxa = p1x * t1.x + p2x * t1.y + cx * t1.z;
            float rya = p1y * t1.x + p2y * t1.y + cy * t1.z;
            float rza = p1z * t1.x + p2z * t1.y + cz * t1.z;
            int rb = O_ROT + ((b * Hh + h) * Ll + l) * 3;
            out[rb + 0] = rxa;
            out[rb + 1] = rya;
            out[rb + 2] = rza;

            float4 t0 = g_t0[h * Ll + l];
            float qw = t0.x, s = t0.y, nwg = t0.z, sc = t0.w;
            float qx = s * rxa, qy = s * rya, qz = s * rza;
            // t = q * (0, p1)
            float tw = -qx*p1x - qy*p1y - qz*p1z;
            float tx =  qw*p1x + qy*p1z - qz*p1y;
            float ty =  qw*p1y + qz*p1x - qx*p1z;
            float tz =  qw*p1z + qx*p1y - qy*p1x;
            // v3 = vec(t * conj(q))
            float vx = -tw*qx + tx*qw - ty*qz + tz*qy;
            float vy = -tw*qy + ty*qw - tz*qx + tx*qz;
            float vz = -tw*qz + tz*qw - tx*qy + ty*qx;
            r[3*l + 0] = (sc * vx + Px) * nwg;
            r[3*l + 1] = (sc * vy + Py) * nwg;
            r[3*l + 2] = (sc * vz + Pz) * nwg;
        }
    }

    // two-phase race-free SMEM scatter: position n gets contributions only
    // from h = n/10 and h = n/10 - 1 (adjacent threads)
    if (active && ((tid & 1) == 0)) {
#pragma unroll
        for (int j = 0; j < 60; j++) acc[30 * tid + j] = r[j];
    }
    __syncthreads();
    if (active && ((tid & 1) == 1)) {
#pragma unroll
        for (int j = 0; j < 60; j++) acc[30 * tid + j] += r[j];
    }
    __syncthreads();

    // writeback: interior positions are exclusively owned by this block;
    // first/last 10 positions overlap neighbor blocks -> atomicAdd (rec is
    // zero-initialized by memset).
    const int gb = (b * Nn + base) * 3;   // O_REC == 0
    for (int f = tid; f < SPANF; f += HBLK) {
        int n = base + f / 3;
        if (n >= Nn) continue;
        float v = acc[f];
        if (f < 30 || f >= SPANF - 30) atomicAdd(&out[gb + f], v);
        else                           out[gb + f] = v;
    }
}

// ---------------------------------------------------------------------------
// k_nw: one block per n, vectorized float4 row writes for nw + contribution
// ---------------------------------------------------------------------------
__device__ __forceinline__ void nw_vals(int h, int ended, int started,
                                        int ha, float wA, float wB,
                                        float& cb, float& nw)
{
    cb = (h >= ended && h < started) ? 1.f : 0.f;
    nw = (h == ha) ? wA : ((h == ha - 1) ? wB : 0.f);
}

__global__ void k_nw(const float* __restrict__ W_enc,
                     float* __restrict__ out)
{
    const int n   = blockIdx.x;
    const int tid = threadIdx.x;
    const int bd  = blockDim.x;

    const int started = (n < Nn - Ll) ? (n / Ss + 1) : Hh;
    const int ended   = (n >= Ll) ? ((n - Ss) / Ss) : 0;
    const int ha = n / Ss, l0 = n % Ss;
    const float inv_rs = 1.f / g_rowsum[n];
    const float wA = (ha < Hh) ? W_enc[(l0 * Hh + ha) * 3] * inv_rs : 0.f;
    const float wB = (ha >= 1) ? W_enc[((l0 + Ss) * Hh + ha - 1) * 3] * inv_rs : 0.f;

    const int bn = O_NW + n * Hh;
    const int bc = O_CB + n * Hh;
    const int head = (4 - (n & 3)) & 3;           // bn,bc ≡ n (mod 4)

    for (int h = tid; h < head; h += bd) {
        float cb, nw; nw_vals(h, ended, started, ha, wA, wB, cb, nw);
        out[bn + h] = nw; out[bc + h] = cb;
    }
    const int nvec = (Hh - head) >> 2;
    float4* vn = (float4*)(out + bn + head);
    float4* vc = (float4*)(out + bc + head);
    for (int v = tid; v < nvec; v += bd) {
        int h = head + 4 * v;
        float4 c4, w4;
        nw_vals(h + 0, ended, started, ha, wA, wB, c4.x, w4.x);
        nw_vals(h + 1, ended, started, ha, wA, wB, c4.y, w4.y);
        nw_vals(h + 2, ended, started, ha, wA, wB, c4.z, w4.z);
        nw_vals(h + 3, ended, started, ha, wA, wB, c4.w, w4.w);
        vn[v] = w4; vc[v] = c4;
    }
    for (int h = head + 4 * nvec + tid; h < Hh; h += bd) {
        float cb, nw; nw_vals(h, ended, started, ha, wA, wB, cb, nw);
        out[bn + h] = nw; out[bc + h] = cb;
    }
}

// ---------------------------------------------------------------------------
extern "C" void kernel_launch(void* const* d_in, const int* in_sizes, int n_in,
                              void* d_out, int out_size)
{
    const float* x       = (const float*)d_in[0];
    const float* W_enc   = (const float*)d_in[1];
    const float* W_dec   = (const float*)d_in[2];
    const float* angles  = (const float*)d_in[3];
    const float* scaling = (const float*)d_in[4];
    float* out = (float*)d_out;

    // zero-init reconstructed region (needed for boundary atomics)
    cudaMemsetAsync(out + O_REC, 0, (size_t)(O_P - O_REC) * sizeof(float));

    k_tables<<<(HL + 255) / 256, 256>>>(angles, W_enc, W_dec, scaling);

    dim3 gA((Hh + HBLK - 1) / HBLK, Bb);
    k_encode<<<gA, HBLK>>>(x, W_enc, out);

    k_nw<<<Nn, 256>>>(W_enc, out);
}